// round 2
// baseline (speedup 1.0000x reference)
#include <cuda_runtime.h>
#include <math.h>

// Problem constants
#define EDIM 1024
#define NH   16
#define DH   64
#define SEQ  2048
#define BATCH 2
#define TOK  (BATCH * SEQ)   // 4096

// Scratch (allocation-free rule: __device__ globals)
__device__ float g_q[TOK * EDIM];    // [B,H,S,DH]
__device__ float g_k[TOK * EDIM];    // [B,H,S,DH]
__device__ float g_v[TOK * EDIM];    // [B,H,S,DH]
__device__ float g_ctx[TOK * EDIM];  // [B,S,E]

// ---------------------------------------------------------------------------
// Shared GEMM body: C = A(4096x1024) @ W(1024x1024) + bias.
// Block tile 128x128, K-tile 8, 256 threads, 8x8 per thread,
// register-prefetch double buffering (next K-tile loads overlap compute).
// SPLIT_HEADS: store [B,H,S,DH] (for q/k/v), else row-major [B,S,E].
// ---------------------------------------------------------------------------
template <bool SPLIT_HEADS>
__device__ __forceinline__
void gemm_body(const float* __restrict__ Ap, const float* __restrict__ Bw,
               const float* __restrict__ bias, float* __restrict__ Cd)
{
    __shared__ float As[8][132];  // transposed A tile, pad -> conflict-free
    __shared__ float Bs[8][128];

    const int tid = threadIdx.x;
    const int tx = tid & 15;        // n fragment
    const int ty = tid >> 4;        // m fragment
    const int m0 = blockIdx.y * 128;
    const int n0 = blockIdx.x * 128;

    float acc[8][8];
#pragma unroll
    for (int i = 0; i < 8; i++)
#pragma unroll
        for (int j = 0; j < 8; j++) acc[i][j] = 0.f;

    const int arow = tid >> 1;           // 0..127
    const int acg  = (tid & 1) * 4;      // 0 or 4
    const int brow = tid >> 5;           // 0..7
    const int bcol = (tid & 31) * 4;     // 0..124
    const float* Aload = Ap + (m0 + arow) * EDIM + acg;
    const float* Bload = Bw + brow * EDIM + n0 + bcol;

    // Prefetch K-tile 0
    float4 av = *(const float4*)(Aload);
    float4 bv = *(const float4*)(Bload);

    for (int k0 = 0; k0 < EDIM; k0 += 8) {
        // Commit prefetched tile to smem
        As[acg + 0][arow] = av.x;
        As[acg + 1][arow] = av.y;
        As[acg + 2][arow] = av.z;
        As[acg + 3][arow] = av.w;
        *(float4*)&Bs[brow][bcol] = bv;
        __syncthreads();

        // Prefetch next K-tile into registers (overlaps with compute below)
        if (k0 + 8 < EDIM) {
            av = *(const float4*)(Aload + (k0 + 8));
            bv = *(const float4*)(Bload + (size_t)(k0 + 8) * EDIM);
        }

#pragma unroll
        for (int kk = 0; kk < 8; kk++) {
            float ra[8], rb[8];
#pragma unroll
            for (int i = 0; i < 8; i++) ra[i] = As[kk][ty * 8 + i];
            float4 b1 = *(const float4*)&Bs[kk][tx * 4];
            float4 b2 = *(const float4*)&Bs[kk][64 + tx * 4];
            rb[0] = b1.x; rb[1] = b1.y; rb[2] = b1.z; rb[3] = b1.w;
            rb[4] = b2.x; rb[5] = b2.y; rb[6] = b2.z; rb[7] = b2.w;
#pragma unroll
            for (int i = 0; i < 8; i++)
#pragma unroll
                for (int j = 0; j < 8; j++) acc[i][j] += ra[i] * rb[j];
        }
        __syncthreads();
    }

    // Epilogue: bias add + store (float4, coalesced)
#pragma unroll
    for (int i = 0; i < 8; i++) {
        const int m = m0 + ty * 8 + i;
#pragma unroll
        for (int half = 0; half < 2; half++) {
            const int n = n0 + half * 64 + tx * 4;
            float4 bb = *(const float4*)(bias + n);
            float4 r;
            r.x = acc[i][half * 4 + 0] + bb.x;
            r.y = acc[i][half * 4 + 1] + bb.y;
            r.z = acc[i][half * 4 + 2] + bb.z;
            r.w = acc[i][half * 4 + 3] + bb.w;
            if (SPLIT_HEADS) {
                const int b = m >> 11, srow = m & 2047;
                const int hh = n >> 6, d = n & 63;
                *(float4*)&Cd[(((b * NH + hh) * SEQ) + srow) * DH + d] = r;
            } else {
                *(float4*)&Cd[m * EDIM + n] = r;
            }
        }
    }
}

// Fused QKV: blockIdx.z in {0,1,2} selects projection. Co-scheduled z-slices
// of the same (m0,n0) improve L2 reuse of x.
__global__ __launch_bounds__(256, 2)
void gemm_qkv(const float* __restrict__ x,
              const float* __restrict__ Wq, const float* __restrict__ bq,
              const float* __restrict__ Wk, const float* __restrict__ bk,
              const float* __restrict__ Wv, const float* __restrict__ bv)
{
    const int z = blockIdx.z;
    const float* W = (z == 0) ? Wq : (z == 1) ? Wk : Wv;
    const float* bb = (z == 0) ? bq : (z == 1) ? bk : bv;
    float* Cd = (z == 0) ? g_q : (z == 1) ? g_k : g_v;
    gemm_body<true>(x, W, bb, Cd);
}

__global__ __launch_bounds__(256, 2)
void gemm_out(const float* __restrict__ Wo, const float* __restrict__ bo,
              float* __restrict__ out)
{
    gemm_body<false>(g_ctx, Wo, bo, out);
}

// ---------------------------------------------------------------------------
// Flash attention, fp32, online softmax.
// Grid: (SEQ/64, B*H). 128 threads = (tx 0..15) x (ty 0..7).
// Each thread: 8 query rows (ty*8+i), 4 key cols (tx+16j), 4 out dims (tx+16j).
// SMEM: Qs[64][68] (Q*0.125), Kt[64(d)][65(key)] reused as P[64(q)][65(k)],
//       Vs[64][68]. Padding chosen for conflict-free hot-loop reads.
// ---------------------------------------------------------------------------
#define ATTN_SMEM_FLOATS (64 * 68 + 64 * 65 + 64 * 68)
#define ATTN_SMEM_BYTES  (ATTN_SMEM_FLOATS * 4)

__global__ __launch_bounds__(128)
void attn_kernel()
{
    extern __shared__ float sm[];
    float* Qs = sm;                 // stride 68
    float* Kt = sm + 64 * 68;       // stride 65 (K transposed, then P)
    float* Vs = Kt + 64 * 65;       // stride 68

    const int tid = threadIdx.x;
    const int tx = tid & 15;
    const int ty = tid >> 4;        // 0..7
    const int bh = blockIdx.y;
    const int q0 = blockIdx.x * 64;
    const float* qb = g_q + (size_t)bh * SEQ * DH;
    const float* kb = g_k + (size_t)bh * SEQ * DH;
    const float* vb = g_v + (size_t)bh * SEQ * DH;

    // Load Q tile once, pre-scaled by 1/sqrt(DH) = 0.125
#pragma unroll
    for (int it = 0; it < 8; it++) {
        const int f4 = it * 128 + tid;
        const int qr = f4 >> 4, dg = (f4 & 15) * 4;
        float4 val = *(const float4*)(qb + (q0 + qr) * DH + dg);
        val.x *= 0.125f; val.y *= 0.125f; val.z *= 0.125f; val.w *= 0.125f;
        *(float4*)&Qs[qr * 68 + dg] = val;
    }

    float mi[8], li[8], o[8][4];
#pragma unroll
    for (int i = 0; i < 8; i++) {
        mi[i] = -1e30f;
        li[i] = 0.f;
#pragma unroll
        for (int j = 0; j < 4; j++) o[i][j] = 0.f;
    }

    for (int kt = 0; kt < SEQ / 64; kt++) {
        __syncthreads();  // previous PV done (and Q visible on first iter)
        const int key0 = kt * 64;
#pragma unroll
        for (int it = 0; it < 8; it++) {
            const int f4 = it * 128 + tid;
            const int key = f4 >> 4, dg = (f4 & 15) * 4;
            float4 kvv = *(const float4*)(kb + (key0 + key) * DH + dg);
            Kt[(dg + 0) * 65 + key] = kvv.x;   // transpose: conflict-free (pad 65)
            Kt[(dg + 1) * 65 + key] = kvv.y;
            Kt[(dg + 2) * 65 + key] = kvv.z;
            Kt[(dg + 3) * 65 + key] = kvv.w;
            float4 vv = *(const float4*)(vb + (key0 + key) * DH + dg);
            *(float4*)&Vs[key * 68 + dg] = vv;
        }
        __syncthreads();

        // Scores: S = (Q/8) @ K^T  -> s[8][4]
        float s[8][4];
#pragma unroll
        for (int i = 0; i < 8; i++)
#pragma unroll
            for (int j = 0; j < 4; j++) s[i][j] = 0.f;

#pragma unroll 8
        for (int kk = 0; kk < 64; kk++) {
            float ra[8], rb[4];
#pragma unroll
            for (int i = 0; i < 8; i++) ra[i] = Qs[(ty * 8 + i) * 68 + kk];   // broadcast
#pragma unroll
            for (int j = 0; j < 4; j++) rb[j] = Kt[kk * 65 + tx + 16 * j];    // conflict-free
#pragma unroll
            for (int i = 0; i < 8; i++)
#pragma unroll
                for (int j = 0; j < 4; j++) s[i][j] += ra[i] * rb[j];
        }

        // Online softmax (row reduction across the 16 tx lanes)
#pragma unroll
        for (int i = 0; i < 8; i++) {
            float tm = fmaxf(fmaxf(s[i][0], s[i][1]), fmaxf(s[i][2], s[i][3]));
#pragma unroll
            for (int off = 1; off < 16; off <<= 1)
                tm = fmaxf(tm, __shfl_xor_sync(0xffffffffu, tm, off));
            const float mn = fmaxf(mi[i], tm);
            const float alpha = __expf(mi[i] - mn);
            float ps = 0.f;
#pragma unroll
            for (int j = 0; j < 4; j++) { s[i][j] = __expf(s[i][j] - mn); ps += s[i][j]; }
#pragma unroll
            for (int off = 1; off < 16; off <<= 1)
                ps += __shfl_xor_sync(0xffffffffu, ps, off);
            li[i] = li[i] * alpha + ps;
            mi[i] = mn;
#pragma unroll
            for (int j = 0; j < 4; j++) o[i][j] *= alpha;
        }

        __syncthreads();  // all Kt reads done before overwriting with P
#pragma unroll
        for (int i = 0; i < 8; i++)
#pragma unroll
            for (int j = 0; j < 4; j++)
                Kt[(ty * 8 + i) * 65 + tx + 16 * j] = s[i][j];
        __syncthreads();

        // O += P @ V
#pragma unroll 8
        for (int kk = 0; kk < 64; kk++) {
            float pv[8], vv[4];
#pragma unroll
            for (int i = 0; i < 8; i++) pv[i] = Kt[(ty * 8 + i) * 65 + kk];   // broadcast
#pragma unroll
            for (int j = 0; j < 4; j++) vv[j] = Vs[kk * 68 + tx + 16 * j];    // conflict-free
#pragma unroll
            for (int i = 0; i < 8; i++)
#pragma unroll
                for (int j = 0; j < 4; j++) o[i][j] += pv[i] * vv[j];
        }
    }

    // Epilogue: normalize, write ctx in [B,S,E] (coalesced over tx)
    const int b = bh >> 4, h = bh & 15;
#pragma unroll
    for (int i = 0; i < 8; i++) {
        const int row = q0 + ty * 8 + i;
        const float inv = 1.f / li[i];
#pragma unroll
        for (int j = 0; j < 4; j++)
            g_ctx[(b * SEQ + row) * EDIM + h * DH + tx + 16 * j] = o[i][j] * inv;
    }
}

// ---------------------------------------------------------------------------
extern "C" void kernel_launch(void* const* d_in, const int* in_sizes, int n_in,
                              void* d_out, int out_size)
{
    const float* x  = (const float*)d_in[0];
    const float* Wq = (const float*)d_in[1];
    const float* bq = (const float*)d_in[2];
    const float* Wk = (const float*)d_in[3];
    const float* bk = (const float*)d_in[4];
    const float* Wv = (const float*)d_in[5];
    const float* bv = (const float*)d_in[6];
    const float* Wo = (const float*)d_in[7];
    const float* bo = (const float*)d_in[8];
    float* out = (float*)d_out;

    cudaFuncSetAttribute(attn_kernel,
                         cudaFuncAttributeMaxDynamicSharedMemorySize,
                         ATTN_SMEM_BYTES);

    dim3 gq(EDIM / 128, TOK / 128, 3);   // fused QKV
    gemm_qkv<<<gq, 256>>>(x, Wq, bq, Wk, bk, Wv, bv);

    attn_kernel<<<dim3(SEQ / 64, BATCH * NH), 128, ATTN_SMEM_BYTES>>>();

    dim3 gg(EDIM / 128, TOK / 128);
    gemm_out<<<gg, 256>>>(Wo, bo, out);
}

// round 5
// speedup vs baseline: 1.4390x; 1.4390x over previous
#include <cuda_runtime.h>
#include <math.h>
#include <stdint.h>

// Problem constants
#define EDIM 1024
#define NH   16
#define DH   64
#define SEQ  2048
#define BATCH 2
#define TOK  (BATCH * SEQ)   // 4096

// Scratch (allocation-free rule: __device__ globals)
__device__ float g_q[TOK * EDIM];    // [B,H,S,DH]
__device__ float g_k[TOK * EDIM];    // [B,H,S,DH]
__device__ float g_v[TOK * EDIM];    // [B,H,S,DH]
__device__ float g_ctx[TOK * EDIM];  // [B,S,E]

// ---------------------------------------------------------------------------
// fp32 SIMT GEMM (unchanged — measured at FFMA roofline, keeps rel_err 6.5e-7)
// C = A(4096x1024) @ W(1024x1024) + bias. Block 128x128, Ktile 8, 256 thr,
// 8x8/thread, register-prefetch double buffering.
// ---------------------------------------------------------------------------
template <bool SPLIT_HEADS>
__device__ __forceinline__
void gemm_body(const float* __restrict__ Ap, const float* __restrict__ Bw,
               const float* __restrict__ bias, float* __restrict__ Cd)
{
    __shared__ float As[8][132];
    __shared__ float Bs[8][128];

    const int tid = threadIdx.x;
    const int tx = tid & 15;
    const int ty = tid >> 4;
    const int m0 = blockIdx.y * 128;
    const int n0 = blockIdx.x * 128;

    float acc[8][8];
#pragma unroll
    for (int i = 0; i < 8; i++)
#pragma unroll
        for (int j = 0; j < 8; j++) acc[i][j] = 0.f;

    const int arow = tid >> 1;
    const int acg  = (tid & 1) * 4;
    const int brow = tid >> 5;
    const int bcol = (tid & 31) * 4;
    const float* Aload = Ap + (m0 + arow) * EDIM + acg;
    const float* Bload = Bw + brow * EDIM + n0 + bcol;

    float4 av = *(const float4*)(Aload);
    float4 bv = *(const float4*)(Bload);

    for (int k0 = 0; k0 < EDIM; k0 += 8) {
        As[acg + 0][arow] = av.x;
        As[acg + 1][arow] = av.y;
        As[acg + 2][arow] = av.z;
        As[acg + 3][arow] = av.w;
        *(float4*)&Bs[brow][bcol] = bv;
        __syncthreads();

        if (k0 + 8 < EDIM) {
            av = *(const float4*)(Aload + (k0 + 8));
            bv = *(const float4*)(Bload + (size_t)(k0 + 8) * EDIM);
        }

#pragma unroll
        for (int kk = 0; kk < 8; kk++) {
            float ra[8], rb[8];
#pragma unroll
            for (int i = 0; i < 8; i++) ra[i] = As[kk][ty * 8 + i];
            float4 b1 = *(const float4*)&Bs[kk][tx * 4];
            float4 b2 = *(const float4*)&Bs[kk][64 + tx * 4];
            rb[0] = b1.x; rb[1] = b1.y; rb[2] = b1.z; rb[3] = b1.w;
            rb[4] = b2.x; rb[5] = b2.y; rb[6] = b2.z; rb[7] = b2.w;
#pragma unroll
            for (int i = 0; i < 8; i++)
#pragma unroll
                for (int j = 0; j < 8; j++) acc[i][j] += ra[i] * rb[j];
        }
        __syncthreads();
    }

#pragma unroll
    for (int i = 0; i < 8; i++) {
        const int m = m0 + ty * 8 + i;
#pragma unroll
        for (int half = 0; half < 2; half++) {
            const int n = n0 + half * 64 + tx * 4;
            float4 bb = *(const float4*)(bias + n);
            float4 r;
            r.x = acc[i][half * 4 + 0] + bb.x;
            r.y = acc[i][half * 4 + 1] + bb.y;
            r.z = acc[i][half * 4 + 2] + bb.z;
            r.w = acc[i][half * 4 + 3] + bb.w;
            if (SPLIT_HEADS) {
                const int b = m >> 11, srow = m & 2047;
                const int hh = n >> 6, d = n & 63;
                *(float4*)&Cd[(((b * NH + hh) * SEQ) + srow) * DH + d] = r;
            } else {
                *(float4*)&Cd[m * EDIM + n] = r;
            }
        }
    }
}

__global__ __launch_bounds__(256, 2)
void gemm_qkv(const float* __restrict__ x,
              const float* __restrict__ Wq, const float* __restrict__ bq,
              const float* __restrict__ Wk, const float* __restrict__ bk,
              const float* __restrict__ Wv, const float* __restrict__ bv)
{
    const int z = blockIdx.z;
    const float* W = (z == 0) ? Wq : (z == 1) ? Wk : Wv;
    const float* bb = (z == 0) ? bq : (z == 1) ? bk : bv;
    float* Cd = (z == 0) ? g_q : (z == 1) ? g_k : g_v;
    gemm_body<true>(x, W, bb, Cd);
}

__global__ __launch_bounds__(256, 2)
void gemm_out(const float* __restrict__ Wo, const float* __restrict__ bo,
              float* __restrict__ out)
{
    gemm_body<false>(g_ctx, Wo, bo, out);
}

// ---------------------------------------------------------------------------
// Flash attention with tf32 mma.sync (m16n8k8), fp32 online softmax.
// CTA: 128 q-rows of one head. 8 warps; warp w owns q-rows [16w, 16w+16).
// Each warp computes its 16x64 S stripe (8 n-tiles), softmax within quads,
// P roundtrip through smem (per-warp private rows -> __syncwarp only),
// then 16x64 O stripe accumulation.
// SMEM strides: 68 for Q/K/P (g*s+t frag pattern conflict-free),
//               72 for V (t*s+g pattern conflict-free).
// K/V register-prefetched one key-tile ahead.
// 105.5KB smem/CTA -> 2 CTAs/SM; regs capped at 128 via launch_bounds.
// ---------------------------------------------------------------------------
#define QS 68
#define VS 72
#define ATTN_SMEM_FLOATS (128*QS + 64*QS + 64*VS + 128*QS)
#define ATTN_SMEM_BYTES  (ATTN_SMEM_FLOATS * 4)

__device__ __forceinline__ uint32_t f2tf32(float x) {
    uint32_t u;
    asm("cvt.rna.tf32.f32 %0, %1;" : "=r"(u) : "f"(x));
    return u;
}
__device__ __forceinline__ float f2tf32f(float x) {
    return __uint_as_float(f2tf32(x));
}

__device__ __forceinline__ void mma8(float* d, const uint32_t* a, const uint32_t* b) {
    asm volatile(
        "mma.sync.aligned.m16n8k8.row.col.f32.tf32.tf32.f32 "
        "{%0,%1,%2,%3},{%4,%5,%6,%7},{%8,%9},{%0,%1,%2,%3};"
        : "+f"(d[0]), "+f"(d[1]), "+f"(d[2]), "+f"(d[3])
        : "r"(a[0]), "r"(a[1]), "r"(a[2]), "r"(a[3]), "r"(b[0]), "r"(b[1]));
}

__global__ __launch_bounds__(256, 2)
void attn_kernel()
{
    extern __shared__ float sm[];
    float* Qs = sm;                  // 128 x QS
    float* Ks = Qs + 128 * QS;       // 64 x QS
    float* Vs = Ks + 64 * QS;        // 64 x VS
    float* Ps = Vs + 64 * VS;        // 128 x QS

    const int tid  = threadIdx.x;
    const int w    = tid >> 5;       // warp 0..7
    const int lane = tid & 31;
    const int g    = lane >> 2;      // 0..7
    const int t    = lane & 3;       // 0..3
    const int bh   = blockIdx.y;
    const int q0   = blockIdx.x * 128;
    const float* qb = g_q + (size_t)bh * SEQ * DH;
    const float* kb = g_k + (size_t)bh * SEQ * DH;
    const float* vb = g_v + (size_t)bh * SEQ * DH;

    // Stage Q once: pre-scale by 1/sqrt(64)=0.125, round to tf32.
#pragma unroll
    for (int it = 0; it < 8; it++) {
        const int idx = it * 256 + tid;      // over 2048 float4
        const int qr = idx >> 4, dg = (idx & 15) * 4;
        float4 v = *(const float4*)(qb + (q0 + qr) * DH + dg);
        Qs[qr * QS + dg + 0] = f2tf32f(v.x * 0.125f);
        Qs[qr * QS + dg + 1] = f2tf32f(v.y * 0.125f);
        Qs[qr * QS + dg + 2] = f2tf32f(v.z * 0.125f);
        Qs[qr * QS + dg + 3] = f2tf32f(v.w * 0.125f);
    }

    // Per-thread state: rows r0 = q0+16w+g, r1 = r0+8
    float O[8][4];
#pragma unroll
    for (int n = 0; n < 8; n++)
#pragma unroll
        for (int j = 0; j < 4; j++) O[n][j] = 0.f;
    float mi0 = -1e30f, mi1 = -1e30f, li0 = 0.f, li1 = 0.f;

    // K/V gmem prefetch registers (one key-tile ahead): 4 float4 each.
    const int pkey = tid >> 2;            // 0..63 (4 threads per row)
    const int pdg  = (tid & 3) * 16;      // 0,16,32,48
    float4 kpre[4], vpre[4];
#pragma unroll
    for (int c = 0; c < 4; c++) {
        kpre[c] = *(const float4*)(kb + pkey * DH + pdg + c * 4);
        vpre[c] = *(const float4*)(vb + pkey * DH + pdg + c * 4);
    }

    for (int kt = 0; kt < SEQ / 64; kt++) {
        __syncthreads();   // all warps done reading Ks/Vs of previous tile

        // Commit prefetched K/V (tf32-rounded)
#pragma unroll
        for (int c = 0; c < 4; c++) {
            const int d0 = pdg + c * 4;
            Ks[pkey * QS + d0 + 0] = f2tf32f(kpre[c].x);
            Ks[pkey * QS + d0 + 1] = f2tf32f(kpre[c].y);
            Ks[pkey * QS + d0 + 2] = f2tf32f(kpre[c].z);
            Ks[pkey * QS + d0 + 3] = f2tf32f(kpre[c].w);
            Vs[pkey * VS + d0 + 0] = f2tf32f(vpre[c].x);
            Vs[pkey * VS + d0 + 1] = f2tf32f(vpre[c].y);
            Vs[pkey * VS + d0 + 2] = f2tf32f(vpre[c].z);
            Vs[pkey * VS + d0 + 3] = f2tf32f(vpre[c].w);
        }
        __syncthreads();

        // Prefetch next key-tile (overlaps with MMA below)
        if (kt + 1 < SEQ / 64) {
            const float* kn = kb + (kt + 1) * 64 * DH;
            const float* vn = vb + (kt + 1) * 64 * DH;
#pragma unroll
            for (int c = 0; c < 4; c++) {
                kpre[c] = *(const float4*)(kn + pkey * DH + pdg + c * 4);
                vpre[c] = *(const float4*)(vn + pkey * DH + pdg + c * 4);
            }
        }

        // ---- S = Q @ K^T (warp stripe 16x64) ----
        float S[8][4];
#pragma unroll
        for (int n = 0; n < 8; n++)
#pragma unroll
            for (int j = 0; j < 4; j++) S[n][j] = 0.f;

#pragma unroll
        for (int ks = 0; ks < 8; ks++) {
            const int kk = ks * 8;
            uint32_t a[4], b[2];
            a[0] = __float_as_uint(Qs[(16 * w + g    ) * QS + kk + t    ]);
            a[1] = __float_as_uint(Qs[(16 * w + g + 8) * QS + kk + t    ]);
            a[2] = __float_as_uint(Qs[(16 * w + g    ) * QS + kk + t + 4]);
            a[3] = __float_as_uint(Qs[(16 * w + g + 8) * QS + kk + t + 4]);
#pragma unroll
            for (int n = 0; n < 8; n++) {
                b[0] = __float_as_uint(Ks[(8 * n + g) * QS + kk + t    ]);
                b[1] = __float_as_uint(Ks[(8 * n + g) * QS + kk + t + 4]);
                mma8(S[n], a, b);
            }
        }

        // ---- Online softmax (rows r0 = regs 0,1; r1 = regs 2,3) ----
        float m0 = -1e30f, m1 = -1e30f;
#pragma unroll
        for (int n = 0; n < 8; n++) {
            m0 = fmaxf(m0, fmaxf(S[n][0], S[n][1]));
            m1 = fmaxf(m1, fmaxf(S[n][2], S[n][3]));
        }
        m0 = fmaxf(m0, __shfl_xor_sync(0xffffffffu, m0, 1));
        m0 = fmaxf(m0, __shfl_xor_sync(0xffffffffu, m0, 2));
        m1 = fmaxf(m1, __shfl_xor_sync(0xffffffffu, m1, 1));
        m1 = fmaxf(m1, __shfl_xor_sync(0xffffffffu, m1, 2));

        const float mn0 = fmaxf(mi0, m0), mn1 = fmaxf(mi1, m1);
        const float al0 = __expf(mi0 - mn0), al1 = __expf(mi1 - mn1);
        mi0 = mn0; mi1 = mn1;

        float ps0 = 0.f, ps1 = 0.f;
        const int r0 = 16 * w + g, r1 = r0 + 8;
#pragma unroll
        for (int n = 0; n < 8; n++) {
            float p00 = f2tf32f(__expf(S[n][0] - mn0));
            float p01 = f2tf32f(__expf(S[n][1] - mn0));
            float p10 = f2tf32f(__expf(S[n][2] - mn1));
            float p11 = f2tf32f(__expf(S[n][3] - mn1));
            ps0 += p00 + p01;
            ps1 += p10 + p11;
            const int c = 8 * n + 2 * t;
            Ps[r0 * QS + c + 0] = p00;
            Ps[r0 * QS + c + 1] = p01;
            Ps[r1 * QS + c + 0] = p10;
            Ps[r1 * QS + c + 1] = p11;
        }
        ps0 += __shfl_xor_sync(0xffffffffu, ps0, 1);
        ps0 += __shfl_xor_sync(0xffffffffu, ps0, 2);
        ps1 += __shfl_xor_sync(0xffffffffu, ps1, 1);
        ps1 += __shfl_xor_sync(0xffffffffu, ps1, 2);
        li0 = li0 * al0 + ps0;
        li1 = li1 * al1 + ps1;

#pragma unroll
        for (int n = 0; n < 8; n++) {
            O[n][0] *= al0; O[n][1] *= al0;
            O[n][2] *= al1; O[n][3] *= al1;
        }

        __syncwarp();   // P rows are warp-private: warp-level visibility suffices

        // ---- O += P @ V (warp stripe 16x64) ----
#pragma unroll
        for (int ks = 0; ks < 8; ks++) {
            const int kk = ks * 8;
            uint32_t a[4], b[2];
            a[0] = __float_as_uint(Ps[(16 * w + g    ) * QS + kk + t    ]);
            a[1] = __float_as_uint(Ps[(16 * w + g + 8) * QS + kk + t    ]);
            a[2] = __float_as_uint(Ps[(16 * w + g    ) * QS + kk + t + 4]);
            a[3] = __float_as_uint(Ps[(16 * w + g + 8) * QS + kk + t + 4]);
#pragma unroll
            for (int n = 0; n < 8; n++) {
                b[0] = __float_as_uint(Vs[(kk + t    ) * VS + 8 * n + g]);
                b[1] = __float_as_uint(Vs[(kk + t + 4) * VS + 8 * n + g]);
                mma8(O[n], a, b);
            }
        }
        __syncwarp();   // P reads complete before next tile overwrites (same warp)
    }

    // Epilogue: normalize, write ctx [B,S,E]
    const int b  = bh >> 4, h = bh & 15;
    const int r0 = q0 + 16 * w + g;
    const float inv0 = 1.f / li0, inv1 = 1.f / li1;
#pragma unroll
    for (int n = 0; n < 8; n++) {
        const int col = h * DH + 8 * n + 2 * t;
        float2 o0 = make_float2(O[n][0] * inv0, O[n][1] * inv0);
        float2 o1 = make_float2(O[n][2] * inv1, O[n][3] * inv1);
        *(float2*)&g_ctx[(size_t)(b * SEQ + r0    ) * EDIM + col] = o0;
        *(float2*)&g_ctx[(size_t)(b * SEQ + r0 + 8) * EDIM + col] = o1;
    }
}

// ---------------------------------------------------------------------------
extern "C" void kernel_launch(void* const* d_in, const int* in_sizes, int n_in,
                              void* d_out, int out_size)
{
    const float* x  = (const float*)d_in[0];
    const float* Wq = (const float*)d_in[1];
    const float* bq = (const float*)d_in[2];
    const float* Wk = (const float*)d_in[3];
    const float* bk = (const float*)d_in[4];
    const float* Wv = (const float*)d_in[5];
    const float* bv = (const float*)d_in[6];
    const float* Wo = (const float*)d_in[7];
    const float* bo = (const float*)d_in[8];
    float* out = (float*)d_out;

    cudaFuncSetAttribute(attn_kernel,
                         cudaFuncAttributeMaxDynamicSharedMemorySize,
                         ATTN_SMEM_BYTES);

    dim3 gq(EDIM / 128, TOK / 128, 3);
    gemm_qkv<<<gq, 256>>>(x, Wq, bq, Wk, bk, Wv, bv);

    attn_kernel<<<dim3(SEQ / 128, BATCH * NH), 256, ATTN_SMEM_BYTES>>>();

    dim3 gg(EDIM / 128, TOK / 128);
    gemm_out<<<gg, 256>>>(Wo, bo, out);
}